// round 16
// baseline (speedup 1.0000x reference)
#include <cuda_runtime.h>
#include <cuda_fp16.h>
#include <cstdint>

#define NN 100000
#define EE 600000
#define DD 128
#define GB 98            // k_deg grid (all blocks resident: 98 <= 148 SMs)
#define GT 1024          // k_deg block
#define SX 136           // smem row stride in words
#define GEMM_SMEM (2 * 64 * SX * 4)   // Xs + Ws, bytes (69632)

// ---- device scratch (allocation-free rule: __device__ globals) ----
__device__ __align__(16) uint32_t g_h1h[(size_t)NN * 64]; // (x@W1)*dinv, fp16x2
__device__ __align__(16) float2 g_h2w[NN];               // layer-2 lin out * dinv
__device__ __align__(16) uint32_t g_w16[64 * DD];        // W1 packed half2 [k2][n]
__device__ int   g_cnt[NN];
__device__ int   g_cur[NN];      // zeroed by k_agg1 each pass
__device__ int   g_off[NN + 1];
__device__ int   g_bsum[GB];
__device__ int   g_csr[EE];
__device__ float g_dinv[NN];
__device__ int   g_ctr[2];       // grid barriers; zeroed by k_agg1 each pass
__device__ int   g_is64;

// ---------------- grid barrier (all GB blocks resident) ----------------
__device__ __forceinline__ void gsync(int idx, int nb) {
    __syncthreads();
    if (threadIdx.x == 0) {
        __threadfence();
        atomicAdd(&g_ctr[idx], 1);
        while (((volatile int*)g_ctr)[idx] < nb) { }
        __threadfence();
    }
    __syncthreads();
}

// ============ k_deg: detect + count + wpack + scan + dinv ============
__global__ void __launch_bounds__(GT) k_deg(const void* __restrict__ ei,
                                            const float* __restrict__ W1,
                                            int n, int e, int nb) {
    __shared__ int s_is64;
    __shared__ int wsum[32];
    __shared__ int s_pre;
    int tid = threadIdx.x, lane = tid & 31, wid = tid >> 5;
    int b = blockIdx.x;
    int gstep = nb * GT;
    int gtid = b * GT + tid;

    if (tid == 0) {
        const unsigned* w = (const unsigned*)ei;
        int all0 = 1;
        for (int j = 1; j < 128; j += 2) all0 &= (w[j] == 0u);
        s_is64 = all0;
        if (b == 0) g_is64 = all0;
    }
    __syncthreads();
    int is64 = s_is64;

    for (int i = gtid; i < e; i += gstep) {
        int t = is64 ? (int)((const long long*)ei)[(long long)e + i]
                     : ((const int*)ei)[e + i];
        if ((unsigned)t < (unsigned)n) atomicAdd(&g_cnt[t], 1);
    }
    for (int i = gtid; i < 64 * DD; i += gstep) {
        int k2 = i >> 7, nn = i & 127;
        __half2 p = __floats2half2_rn(W1[(2 * k2) * DD + nn],
                                      W1[(2 * k2 + 1) * DD + nn]);
        g_w16[i] = *(uint32_t*)&p;
    }
    gsync(0, nb);

    int i = b * GT + tid;
    int v = (i < n) ? g_cnt[i] : 0;
    int incl = v;
#pragma unroll
    for (int d = 1; d < 32; d <<= 1) {
        int y = __shfl_up_sync(0xffffffffu, incl, d);
        if (lane >= d) incl += y;
    }
    if (lane == 31) wsum[wid] = incl;
    __syncthreads();
    if (wid == 0) {
        int s = wsum[lane];
#pragma unroll
        for (int d = 1; d < 32; d <<= 1) {
            int y = __shfl_up_sync(0xffffffffu, s, d);
            if (lane >= d) s += y;
        }
        wsum[lane] = s;
    }
    __syncthreads();
    int wprev = wid ? wsum[wid - 1] : 0;
    int excl = wprev + incl - v;
    if (i < n) g_off[i] = excl;
    if (tid == GT - 1) g_bsum[b] = wprev + incl;
    gsync(1, nb);

    if (tid == 0) {
        int p = 0;
        for (int j = 0; j < b; j++) p += g_bsum[j];
        s_pre = p;
        if (b == nb - 1) g_off[n] = p + g_bsum[b];
    }
    __syncthreads();
    if (i < n) {
        g_off[i] += s_pre;
        g_dinv[i] = rsqrtf((float)(g_cnt[i] + 1));   // +1 = self-loop
        g_cnt[i] = 0;
    }
}

// ---------------- k_fill: CSR fill ----------------
__global__ void k_fill(const void* __restrict__ ei, int e, int n) {
    int i = blockIdx.x * blockDim.x + threadIdx.x;
    if (i >= e) return;
    int is64 = g_is64;
    int t = is64 ? (int)((const long long*)ei)[(long long)e + i]
                 : ((const int*)ei)[e + i];
    int s = is64 ? (int)((const long long*)ei)[i]
                 : ((const int*)ei)[i];
    if ((unsigned)t < (unsigned)n && (unsigned)s < (unsigned)n) {
        int p = atomicAdd(&g_cur[t], 1);
        g_csr[g_off[t] + p] = s;
    }
}

// ---------------- fp16 mma ----------------
__device__ __forceinline__ void mma16(float* c, const uint32_t* a, const uint32_t* b) {
    asm volatile(
        "mma.sync.aligned.m16n8k16.row.col.f32.f16.f16.f32 "
        "{%0,%1,%2,%3},{%4,%5,%6,%7},{%8,%9},{%0,%1,%2,%3};"
        : "+f"(c[0]), "+f"(c[1]), "+f"(c[2]), "+f"(c[3])
        : "r"(a[0]), "r"(a[1]), "r"(a[2]), "r"(a[3]), "r"(b[0]), "r"(b[1]));
}

// --- GEMM1: full-K in smem, ONE sync, fp16 MMA; epilogue scales by dinv ---
__global__ void __launch_bounds__(256, 2)
k_gemm1_tc(const float* __restrict__ x, int n) {
    extern __shared__ uint32_t smem[];
    uint32_t* Xs = smem;                 // 64 k2 x 128 rows (swizzled)
    uint32_t* Ws = smem + 64 * SX;       // 64 k2 x 128 cols (swizzled)
    int tid = threadIdx.x;
    int wid = tid >> 5, lane = tid & 31;
    int gid = lane >> 2, tig = lane & 3;
    int warpM = wid & 3;
    int warpN = wid >> 2;
    int row0 = blockIdx.x * 128;

    float acc[2][8][4];
#pragma unroll
    for (int mt = 0; mt < 2; mt++)
#pragma unroll
        for (int nt = 0; nt < 8; nt++)
#pragma unroll
            for (int j = 0; j < 4; j++) acc[mt][nt][j] = 0.f;

#pragma unroll
    for (int j = 0; j < 16; j++) {
        int idx = tid + j * 256;          // 4096 float4
        int r = idx >> 5, q = idx & 31;
        float4 v = make_float4(0.f, 0.f, 0.f, 0.f);
        if (row0 + r < n)
            v = *(const float4*)(x + (size_t)(row0 + r) * DD + q * 4);
        __half2 p0 = __floats2half2_rn(v.x, v.y);
        __half2 p1 = __floats2half2_rn(v.z, v.w);
        int rs = r ^ q;
        Xs[(2 * q) * SX + rs]     = *(uint32_t*)&p0;
        Xs[(2 * q + 1) * SX + rs] = *(uint32_t*)&p1;
    }
#pragma unroll
    for (int j = 0; j < 32; j++) {
        int idx = tid + j * 256;          // 8192 words
        int k2 = idx >> 7, nn = idx & 127;
        uint32_t w = g_w16[idx];
        Ws[k2 * SX + (nn ^ ((k2 >> 1) & 31))] = w;
    }
    __syncthreads();

#pragma unroll
    for (int ks = 0; ks < 8; ks++) {
        int m0 = ks * 4 + (tig >> 1);
        int m1 = m0 + 2;
        int k2a = ks * 8 + tig, k2b = k2a + 4;
        uint32_t a[2][4];
#pragma unroll
        for (int mt = 0; mt < 2; mt++) {
            int rb = warpM * 32 + mt * 16 + gid;
            a[mt][0] = Xs[k2a * SX + (rb ^ m0)];
            a[mt][1] = Xs[k2a * SX + ((rb + 8) ^ m0)];
            a[mt][2] = Xs[k2b * SX + (rb ^ m1)];
            a[mt][3] = Xs[k2b * SX + ((rb + 8) ^ m1)];
        }
#pragma unroll
        for (int nt = 0; nt < 8; nt++) {
            int nb = warpN * 64 + nt * 8 + gid;
            uint32_t b[2];
            b[0] = Ws[k2a * SX + (nb ^ m0)];
            b[1] = Ws[k2b * SX + (nb ^ m1)];
#pragma unroll
            for (int mt = 0; mt < 2; mt++)
                mma16(acc[mt][nt], a[mt], b);
        }
    }

#pragma unroll
    for (int mt = 0; mt < 2; mt++) {
        int rowA = row0 + warpM * 32 + mt * 16 + gid;
        int rowB = rowA + 8;
        float dA = (rowA < n) ? g_dinv[rowA] : 0.f;
        float dB = (rowB < n) ? g_dinv[rowB] : 0.f;
#pragma unroll
        for (int nt = 0; nt < 8; nt++) {
            int h2c = warpN * 32 + nt * 4 + tig;
            if (rowA < n) {
                __half2 p = __floats2half2_rn(acc[mt][nt][0] * dA, acc[mt][nt][1] * dA);
                g_h1h[(size_t)rowA * 64 + h2c] = *(uint32_t*)&p;
            }
            if (rowB < n) {
                __half2 p = __floats2half2_rn(acc[mt][nt][2] * dB, acc[mt][nt][3] * dB);
                g_h1h[(size_t)rowB * 64 + h2c] = *(uint32_t*)&p;
            }
        }
    }
}

__device__ __forceinline__ __half2 u2h(uint32_t u) { return *(__half2*)&u; }

__device__ __forceinline__ void acc_u4(uint4 v, float* a) {
    float2 f0 = __half22float2(u2h(v.x));
    float2 f1 = __half22float2(u2h(v.y));
    float2 f2 = __half22float2(u2h(v.z));
    float2 f3 = __half22float2(u2h(v.w));
    a[0] += f0.x; a[1] += f0.y; a[2] += f1.x; a[3] += f1.y;
    a[4] += f2.x; a[5] += f2.y; a[6] += f3.x; a[7] += f3.y;
}

// ------- agg1: HALF-WARP per node, uint4 gathers; bias+relu+W2 fused -------
__global__ void __launch_bounds__(256) k_agg1(const float* __restrict__ b1,
                                              const float* __restrict__ W2, int n) {
    int gwarp = (blockIdx.x * blockDim.x + threadIdx.x) >> 5;
    int lane = threadIdx.x & 31;
    int half = lane >> 4, hl = lane & 15, hb = half << 4;
    int node = gwarp * 2 + half;
    bool act = node < n;
    if (hl == 0 && act) {
        g_cur[node] = 0;
        if (node == 0) { g_ctr[0] = 0; g_ctr[1] = 0; }
    }
    float dn = act ? g_dinv[node] : 0.f;
    const uint4* h4 = (const uint4*)g_h1h;    // 16 x 16B chunks per row
    float a[8] = {0.f, 0.f, 0.f, 0.f, 0.f, 0.f, 0.f, 0.f};
    if (act) {                                 // self (pre-scaled)
        uint4 sv = __ldcg(h4 + (size_t)node * 16 + hl);
        acc_u4(sv, a);
    }
    int e0 = 0, e1 = 0;
    if (act) { e0 = g_off[node]; e1 = g_off[node + 1]; }
    int deg = e1 - e0;
    int myidx = (hl < deg) ? g_csr[e0 + hl] : 0;   // coalesced idx preload
    int full = deg < 16 ? deg : 16;
    int mx = full;
    mx = max(mx, __shfl_xor_sync(0xffffffffu, mx, 16));   // uniform bound
    for (int j = 0; j < mx; j += 2) {
        int s0 = __shfl_sync(0xffffffffu, myidx, (j & 15) + hb);
        int s1 = __shfl_sync(0xffffffffu, myidx, ((j + 1) & 15) + hb);
        uint4 v0 = make_uint4(0, 0, 0, 0), v1 = make_uint4(0, 0, 0, 0);
        if (j < full)     v0 = __ldcg(h4 + (size_t)s0 * 16 + hl);
        if (j + 1 < full) v1 = __ldcg(h4 + (size_t)s1 * 16 + hl);
        __half2 h0 = __hadd2(u2h(v0.x), u2h(v1.x));
        __half2 h1 = __hadd2(u2h(v0.y), u2h(v1.y));
        __half2 h2 = __hadd2(u2h(v0.z), u2h(v1.z));
        __half2 h3 = __hadd2(u2h(v0.w), u2h(v1.w));
        float2 f0 = __half22float2(h0), f1 = __half22float2(h1);
        float2 f2 = __half22float2(h2), f3 = __half22float2(h3);
        a[0] += f0.x; a[1] += f0.y; a[2] += f1.x; a[3] += f1.y;
        a[4] += f2.x; a[5] += f2.y; a[6] += f3.x; a[7] += f3.y;
    }
    for (int e = e0 + 16; e < e1; e++) {       // deg>16 tail (rare, shfl-free)
        uint4 v = __ldcg(h4 + (size_t)g_csr[e] * 16 + hl);
        acc_u4(v, a);
    }
    // bias + relu  (features hl*8 .. hl*8+7)
    float4 bA = ((const float4*)b1)[hl * 2];
    float4 bB = ((const float4*)b1)[hl * 2 + 1];
    float v0 = fmaxf(a[0] * dn + bA.x, 0.f);
    float v1 = fmaxf(a[1] * dn + bA.y, 0.f);
    float v2 = fmaxf(a[2] * dn + bA.z, 0.f);
    float v3 = fmaxf(a[3] * dn + bA.w, 0.f);
    float v4 = fmaxf(a[4] * dn + bB.x, 0.f);
    float v5 = fmaxf(a[5] * dn + bB.y, 0.f);
    float v6 = fmaxf(a[6] * dn + bB.z, 0.f);
    float v7 = fmaxf(a[7] * dn + bB.w, 0.f);
    // W2 projection (rows hl*8..+7, 2 cols each)
    const float4* w4 = (const float4*)W2;
    float4 wA = w4[hl * 4], wB = w4[hl * 4 + 1];
    float4 wC = w4[hl * 4 + 2], wD = w4[hl * 4 + 3];
    float o0 = v0 * wA.x + v1 * wA.z + v2 * wB.x + v3 * wB.z
             + v4 * wC.x + v5 * wC.z + v6 * wD.x + v7 * wD.z;
    float o1 = v0 * wA.y + v1 * wA.w + v2 * wB.y + v3 * wB.w
             + v4 * wC.y + v5 * wC.w + v6 * wD.y + v7 * wD.w;
#pragma unroll
    for (int d = 1; d < 16; d <<= 1) {         // reduce within 16-lane half
        o0 += __shfl_xor_sync(0xffffffffu, o0, d);
        o1 += __shfl_xor_sync(0xffffffffu, o1, d);
    }
    if (hl == 0 && act)
        g_h2w[node] = make_float2(o0 * dn, o1 * dn);   // pre-scale for L2
}

// ---------------- agg2: thread per node, unroll-4 ----------------
__global__ void k_agg2(const float* __restrict__ b2, float* __restrict__ out, int n) {
    int i = blockIdx.x * blockDim.x + threadIdx.x;
    if (i >= n) return;
    float dn = g_dinv[i];
    float2 hv = g_h2w[i];
    float p0 = hv.x, p1 = hv.y;                 // self (pre-scaled)
    float q0 = 0.f, q1 = 0.f;
    int e0 = g_off[i], e1 = g_off[i + 1];
    int e = e0;
    for (; e + 3 < e1; e += 4) {
        int s0 = g_csr[e], s1 = g_csr[e + 1], s2 = g_csr[e + 2], s3 = g_csr[e + 3];
        float2 v0 = g_h2w[s0], v1 = g_h2w[s1], v2 = g_h2w[s2], v3 = g_h2w[s3];
        p0 += v0.x; p1 += v0.y;
        q0 += v1.x; q1 += v1.y;
        p0 += v2.x; p1 += v2.y;
        q0 += v3.x; q1 += v3.y;
    }
    for (; e < e1; e++) {
        float2 v0 = g_h2w[g_csr[e]];
        p0 += v0.x; p1 += v0.y;
    }
    ((float2*)out)[i] = make_float2((p0 + q0) * dn + b2[0], (p1 + q1) * dn + b2[1]);
}

// ---------------- launch (single stream) ----------------
extern "C" void kernel_launch(void* const* d_in, const int* in_sizes, int n_in,
                              void* d_out, int out_size) {
    const float* x  = (const float*)d_in[0];
    const void*  ei = d_in[1];
    const float* W1 = (const float*)d_in[2];
    const float* b1 = (const float*)d_in[3];
    const float* W2 = (const float*)d_in[4];
    const float* b2 = (const float*)d_in[5];
    float* out = (float*)d_out;

    const int n = in_sizes[0] / DD;       // 100000
    const int e = in_sizes[1] / 2;        // 600000

    cudaFuncSetAttribute(k_gemm1_tc,
                         cudaFuncAttributeMaxDynamicSharedMemorySize, GEMM_SMEM);

    k_deg<<<GB, GT>>>(ei, W1, n, e, GB);
    k_fill<<<(e + 255) / 256, 256>>>(ei, e, n);
    k_gemm1_tc<<<(n + 127) / 128, 256, GEMM_SMEM>>>(x, n);
    k_agg1<<<(n + 15) / 16, 256>>>(b1, W2, n);
    k_agg2<<<(n + 255) / 256, 256>>>(b2, out, n);
}

// round 17
// speedup vs baseline: 1.0430x; 1.0430x over previous
#include <cuda_runtime.h>
#include <cuda_fp16.h>
#include <cstdint>

#define NN 100000
#define EE 600000
#define DD 128
#define SCAN_B 1024
#define NBLK ((NN + SCAN_B - 1) / SCAN_B)   // 98
#define SX 136
#define GEMM_SMEM (2 * 64 * SX * 4)   // 69632 B

// ---- device scratch ----
__device__ __align__(16) uint32_t g_h1h[(size_t)NN * 64]; // x@W1 raw, fp16x2
__device__ __align__(16) float2 g_h2w[NN];               // layer-2 lin out * dinv
__device__ __align__(16) uint32_t g_w16[64 * DD];        // W1 packed half2 [k2][n]
__device__ int   g_cnt[NN];      // zeroed by k_scan3 after use
__device__ int   g_cur[NN];      // zeroed by k_agg1 each pass
__device__ int   g_off[NN + 1];
__device__ int   g_bsum[NBLK + 1];
__device__ int   g_csr[EE];
__device__ float g_dinv[NN];
__device__ int   g_is64;

// ---------------- edge dtype detect ----------------
__global__ void k_detect(const unsigned* __restrict__ w) {
    if (threadIdx.x == 0) {
        int all0 = 1;
        for (int j = 1; j < 128; j += 2) all0 &= (w[j] == 0u);
        g_is64 = all0;
    }
}

__global__ void k_count(const void* __restrict__ ei, int e, int n) {
    int i = blockIdx.x * blockDim.x + threadIdx.x;
    if (i >= e) return;
    int is64 = g_is64;
    int t = is64 ? (int)((const long long*)ei)[(long long)e + i]
                 : ((const int*)ei)[e + i];
    if ((unsigned)t < (unsigned)n) atomicAdd(&g_cnt[t], 1);
}

__global__ void k_scan1(int n) {
    __shared__ int wsum[32];
    int tid = threadIdx.x, lane = tid & 31, wid = tid >> 5;
    int i = blockIdx.x * SCAN_B + tid;
    int v = (i < n) ? g_cnt[i] : 0;
    int incl = v;
#pragma unroll
    for (int d = 1; d < 32; d <<= 1) {
        int y = __shfl_up_sync(0xffffffffu, incl, d);
        if (lane >= d) incl += y;
    }
    if (lane == 31) wsum[wid] = incl;
    __syncthreads();
    if (wid == 0) {
        int s = wsum[lane];
#pragma unroll
        for (int d = 1; d < 32; d <<= 1) {
            int y = __shfl_up_sync(0xffffffffu, s, d);
            if (lane >= d) s += y;
        }
        wsum[lane] = s;
    }
    __syncthreads();
    int wprev = wid ? wsum[wid - 1] : 0;
    if (i < n) g_off[i] = wprev + incl - v;
    if (tid == SCAN_B - 1) g_bsum[blockIdx.x] = wprev + incl;
}

__global__ void k_scan2(int nb) {
    __shared__ int wsum[4];
    int tid = threadIdx.x, lane = tid & 31, wid = tid >> 5;
    int v = (tid < nb) ? g_bsum[tid] : 0;
    int incl = v;
#pragma unroll
    for (int d = 1; d < 32; d <<= 1) {
        int y = __shfl_up_sync(0xffffffffu, incl, d);
        if (lane >= d) incl += y;
    }
    if (lane == 31) wsum[wid] = incl;
    __syncthreads();
    int wprev = 0;
    for (int j = 0; j < wid; j++) wprev += wsum[j];
    int excl = wprev + incl - v;
    if (tid < nb) g_bsum[tid] = excl;
    if (tid == nb - 1) g_bsum[nb] = wprev + incl;
}

__global__ void k_scan3(int n, int nb) {
    int i = blockIdx.x * SCAN_B + threadIdx.x;
    if (i < n) {
        g_off[i] += g_bsum[blockIdx.x];
        g_dinv[i] = rsqrtf((float)(g_cnt[i] + 1));   // +1 = self-loop
        g_cnt[i] = 0;                                // reset for next replay
    }
    if (i == 0) g_off[n] = g_bsum[nb];
}

__global__ void k_fill(const void* __restrict__ ei, int e, int n) {
    int i = blockIdx.x * blockDim.x + threadIdx.x;
    if (i >= e) return;
    int is64 = g_is64;
    int t = is64 ? (int)((const long long*)ei)[(long long)e + i]
                 : ((const int*)ei)[e + i];
    int s = is64 ? (int)((const long long*)ei)[i]
                 : ((const int*)ei)[i];
    if ((unsigned)t < (unsigned)n && (unsigned)s < (unsigned)n) {
        int p = atomicAdd(&g_cur[t], 1);
        g_csr[g_off[t] + p] = s;
    }
}

// ---------------- W1 fp16 pack ----------------
__global__ void k_wpack(const float* __restrict__ W1) {
    int i = blockIdx.x * blockDim.x + threadIdx.x;
    if (i < 64 * DD) {
        int k2 = i >> 7, nn = i & 127;
        __half2 p = __floats2half2_rn(W1[(2 * k2) * DD + nn],
                                      W1[(2 * k2 + 1) * DD + nn]);
        g_w16[i] = *(uint32_t*)&p;
    }
}

// ---------------- fp16 mma ----------------
__device__ __forceinline__ void mma16(float* c, const uint32_t* a, const uint32_t* b) {
    asm volatile(
        "mma.sync.aligned.m16n8k16.row.col.f32.f16.f16.f32 "
        "{%0,%1,%2,%3},{%4,%5,%6,%7},{%8,%9},{%0,%1,%2,%3};"
        : "+f"(c[0]), "+f"(c[1]), "+f"(c[2]), "+f"(c[3])
        : "r"(a[0]), "r"(a[1]), "r"(a[2]), "r"(a[3]), "r"(b[0]), "r"(b[1]));
}

// --- GEMM1: full-K smem, ONE sync, fp16 MMA; stores RAW h1 (no dinv) ---
__global__ void __launch_bounds__(256, 2)
k_gemm1_tc(const float* __restrict__ x, int n) {
    extern __shared__ uint32_t smem[];
    uint32_t* Xs = smem;
    uint32_t* Ws = smem + 64 * SX;
    int tid = threadIdx.x;
    int wid = tid >> 5, lane = tid & 31;
    int gid = lane >> 2, tig = lane & 3;
    int warpM = wid & 3;
    int warpN = wid >> 2;
    int row0 = blockIdx.x * 128;

    float acc[2][8][4];
#pragma unroll
    for (int mt = 0; mt < 2; mt++)
#pragma unroll
        for (int nt = 0; nt < 8; nt++)
#pragma unroll
            for (int j = 0; j < 4; j++) acc[mt][nt][j] = 0.f;

#pragma unroll
    for (int j = 0; j < 16; j++) {
        int idx = tid + j * 256;
        int r = idx >> 5, q = idx & 31;
        float4 v = make_float4(0.f, 0.f, 0.f, 0.f);
        if (row0 + r < n)
            v = *(const float4*)(x + (size_t)(row0 + r) * DD + q * 4);
        __half2 p0 = __floats2half2_rn(v.x, v.y);
        __half2 p1 = __floats2half2_rn(v.z, v.w);
        int rs = r ^ q;
        Xs[(2 * q) * SX + rs]     = *(uint32_t*)&p0;
        Xs[(2 * q + 1) * SX + rs] = *(uint32_t*)&p1;
    }
#pragma unroll
    for (int j = 0; j < 32; j++) {
        int idx = tid + j * 256;
        int k2 = idx >> 7, nn = idx & 127;
        uint32_t w = g_w16[idx];
        Ws[k2 * SX + (nn ^ ((k2 >> 1) & 31))] = w;
    }
    __syncthreads();

#pragma unroll
    for (int ks = 0; ks < 8; ks++) {
        int m0 = ks * 4 + (tig >> 1);
        int m1 = m0 + 2;
        int k2a = ks * 8 + tig, k2b = k2a + 4;
        uint32_t a[2][4];
#pragma unroll
        for (int mt = 0; mt < 2; mt++) {
            int rb = warpM * 32 + mt * 16 + gid;
            a[mt][0] = Xs[k2a * SX + (rb ^ m0)];
            a[mt][1] = Xs[k2a * SX + ((rb + 8) ^ m0)];
            a[mt][2] = Xs[k2b * SX + (rb ^ m1)];
            a[mt][3] = Xs[k2b * SX + ((rb + 8) ^ m1)];
        }
#pragma unroll
        for (int nt = 0; nt < 8; nt++) {
            int nb = warpN * 64 + nt * 8 + gid;
            uint32_t b[2];
            b[0] = Ws[k2a * SX + (nb ^ m0)];
            b[1] = Ws[k2b * SX + (nb ^ m1)];
#pragma unroll
            for (int mt = 0; mt < 2; mt++)
                mma16(acc[mt][nt], a[mt], b);
        }
    }

#pragma unroll
    for (int mt = 0; mt < 2; mt++) {
        int rowA = row0 + warpM * 32 + mt * 16 + gid;
        int rowB = rowA + 8;
#pragma unroll
        for (int nt = 0; nt < 8; nt++) {
            int h2c = warpN * 32 + nt * 4 + tig;
            if (rowA < n) {
                __half2 p = __floats2half2_rn(acc[mt][nt][0], acc[mt][nt][1]);
                g_h1h[(size_t)rowA * 64 + h2c] = *(uint32_t*)&p;
            }
            if (rowB < n) {
                __half2 p = __floats2half2_rn(acc[mt][nt][2], acc[mt][nt][3]);
                g_h1h[(size_t)rowB * 64 + h2c] = *(uint32_t*)&p;
            }
        }
    }
}

__device__ __forceinline__ __half2 u2h(uint32_t u) { return *(__half2*)&u; }

__device__ __forceinline__ void accw(uint4 v, float w, float* a) {
    float2 f0 = __half22float2(u2h(v.x));
    float2 f1 = __half22float2(u2h(v.y));
    float2 f2 = __half22float2(u2h(v.z));
    float2 f3 = __half22float2(u2h(v.w));
    a[0] += f0.x * w; a[1] += f0.y * w; a[2] += f1.x * w; a[3] += f1.y * w;
    a[4] += f2.x * w; a[5] += f2.y * w; a[6] += f3.x * w; a[7] += f3.y * w;
}

// ------- agg1: half-warp/node; shuffled idx+dinv preload; weighted gathers -------
__global__ void __launch_bounds__(256) k_agg1(const float* __restrict__ b1,
                                              const float* __restrict__ W2, int n) {
    int gwarp = (blockIdx.x * blockDim.x + threadIdx.x) >> 5;
    int lane = threadIdx.x & 31;
    int half = lane >> 4, hl = lane & 15, hb = half << 4;
    int node = gwarp * 2 + half;
    bool act = node < n;
    if (hl == 0 && act) g_cur[node] = 0;     // reset for next replay
    float dn = act ? g_dinv[node] : 0.f;
    const uint4* h4 = (const uint4*)g_h1h;   // 16 x 16B chunks per row
    float a[8] = {0.f, 0.f, 0.f, 0.f, 0.f, 0.f, 0.f, 0.f};
    if (act) {                                // self: weight dn^2
        uint4 sv = __ldcg(h4 + (size_t)node * 16 + hl);
        accw(sv, dn * dn, a);
    }
    int e0 = 0, e1 = 0;
    if (act) { e0 = g_off[node]; e1 = g_off[node + 1]; }
    int deg = e1 - e0;
    int myidx = 0;
    float mydv = 0.f;
    if (hl < deg) {
        myidx = g_csr[e0 + hl];
        mydv = g_dinv[myidx];
    }
    int full = deg < 16 ? deg : 16;
    int mx = full;
    mx = max(mx, __shfl_xor_sync(0xffffffffu, mx, 16));   // uniform bound
    for (int j = 0; j < mx; j++) {
        int s = __shfl_sync(0xffffffffu, myidx, (j & 15) + hb);
        float w = __shfl_sync(0xffffffffu, mydv, (j & 15) + hb) * dn;
        if (j < full) {
            uint4 v = __ldcg(h4 + (size_t)s * 16 + hl);
            accw(v, w, a);
        }
    }
    for (int e = e0 + 16; e < e1; e++) {      // deg>16 tail (rare)
        int s = g_csr[e];
        float w = g_dinv[s] * dn;
        uint4 v = __ldcg(h4 + (size_t)s * 16 + hl);
        accw(v, w, a);
    }
    // bias + relu  (features hl*8 .. hl*8+7); weights already applied
    float4 bA = ((const float4*)b1)[hl * 2];
    float4 bB = ((const float4*)b1)[hl * 2 + 1];
    float v0 = fmaxf(a[0] + bA.x, 0.f);
    float v1 = fmaxf(a[1] + bA.y, 0.f);
    float v2 = fmaxf(a[2] + bA.z, 0.f);
    float v3 = fmaxf(a[3] + bA.w, 0.f);
    float v4 = fmaxf(a[4] + bB.x, 0.f);
    float v5 = fmaxf(a[5] + bB.y, 0.f);
    float v6 = fmaxf(a[6] + bB.z, 0.f);
    float v7 = fmaxf(a[7] + bB.w, 0.f);
    // W2 projection (rows hl*8..+7, 2 cols each)
    const float4* w4 = (const float4*)W2;
    float4 wA = w4[hl * 4], wB = w4[hl * 4 + 1];
    float4 wC = w4[hl * 4 + 2], wD = w4[hl * 4 + 3];
    float o0 = v0 * wA.x + v1 * wA.z + v2 * wB.x + v3 * wB.z
             + v4 * wC.x + v5 * wC.z + v6 * wD.x + v7 * wD.z;
    float o1 = v0 * wA.y + v1 * wA.w + v2 * wB.y + v3 * wB.w
             + v4 * wC.y + v5 * wC.w + v6 * wD.y + v7 * wD.w;
#pragma unroll
    for (int d = 1; d < 16; d <<= 1) {
        o0 += __shfl_xor_sync(0xffffffffu, o0, d);
        o1 += __shfl_xor_sync(0xffffffffu, o1, d);
    }
    if (hl == 0 && act)
        g_h2w[node] = make_float2(o0 * dn, o1 * dn);   // pre-scale for layer 2
}

// ---------------- agg2: thread per node, unroll-4 ----------------
__global__ void k_agg2(const float* __restrict__ b2, float* __restrict__ out, int n) {
    int i = blockIdx.x * blockDim.x + threadIdx.x;
    if (i >= n) return;
    float dn = g_dinv[i];
    float2 hv = g_h2w[i];
    float p0 = hv.x, p1 = hv.y;                 // self (pre-scaled)
    float q0 = 0.f, q1 = 0.f;
    int e0 = g_off[i], e1 = g_off[i + 1];
    int e = e0;
    for (; e + 3 < e1; e += 4) {
        int s0 = g_csr[e], s1 = g_csr[e + 1], s2 = g_csr[e + 2], s3 = g_csr[e + 3];
        float2 v0 = g_h2w[s0], v1 = g_h2w[s1], v2 = g_h2w[s2], v3 = g_h2w[s3];
        p0 += v0.x; p1 += v0.y;
        q0 += v1.x; q1 += v1.y;
        p0 += v2.x; p1 += v2.y;
        q0 += v3.x; q1 += v3.y;
    }
    for (; e < e1; e++) {
        float2 v0 = g_h2w[g_csr[e]];
        p0 += v0.x; p1 += v0.y;
    }
    ((float2*)out)[i] = make_float2((p0 + q0) * dn + b2[0], (p1 + q1) * dn + b2[1]);
}

// ---------------- launch: CSR chain (s2) ∥ wpack+gemm (legacy) ----------------
extern "C" void kernel_launch(void* const* d_in, const int* in_sizes, int n_in,
                              void* d_out, int out_size) {
    const float* x  = (const float*)d_in[0];
    const void*  ei = d_in[1];
    const float* W1 = (const float*)d_in[2];
    const float* b1 = (const float*)d_in[3];
    const float* W2 = (const float*)d_in[4];
    const float* b2 = (const float*)d_in[5];
    float* out = (float*)d_out;

    const int n = in_sizes[0] / DD;       // 100000
    const int e = in_sizes[1] / 2;        // 600000
    const int nb = (n + SCAN_B - 1) / SCAN_B;

    cudaFuncSetAttribute(k_gemm1_tc,
                         cudaFuncAttributeMaxDynamicSharedMemorySize, GEMM_SMEM);

    cudaStream_t s2;
    cudaStreamCreateWithFlags(&s2, cudaStreamNonBlocking);
    cudaEvent_t ev0, ev2;
    cudaEventCreateWithFlags(&ev0, cudaEventDisableTiming);
    cudaEventCreateWithFlags(&ev2, cudaEventDisableTiming);

    // fork
    cudaEventRecord(ev0, 0);
    cudaStreamWaitEvent(s2, ev0, 0);

    // s2: CSR chain (small sequential kernels, no grid barriers)
    k_detect<<<1, 32, 0, s2>>>((const unsigned*)ei);
    k_count<<<(e + 255) / 256, 256, 0, s2>>>(ei, e, n);
    k_scan1<<<nb, SCAN_B, 0, s2>>>(n);
    k_scan2<<<1, 128, 0, s2>>>(nb);
    k_scan3<<<nb, SCAN_B, 0, s2>>>(n, nb);
    k_fill<<<(e + 255) / 256, 256, 0, s2>>>(ei, e, n);
    cudaEventRecord(ev2, s2);

    // legacy: W pack + GEMM (independent of CSR)
    k_wpack<<<(64 * DD + 255) / 256, 256>>>(W1);
    k_gemm1_tc<<<(n + 127) / 128, 256, GEMM_SMEM>>>(x, n);

    // join, then aggregation
    cudaStreamWaitEvent(0, ev2, 0);
    k_agg1<<<(n + 15) / 16, 256>>>(b1, W2, n);
    k_agg2<<<(n + 255) / 256, 256>>>(b2, out, n);
}